// round 1
// baseline (speedup 1.0000x reference)
#include <cuda_runtime.h>

// Problem constants (fixed by the dataset)
#define NNODES 50000
#define NEDGES 800000
#define NTOT   (NEDGES + NNODES)   // edges + self loops = 850000
#define D      64
#define H      4
#define HD     256                 // H*D

// -------- scratch (static device globals; no allocation allowed) --------
__device__ __align__(16) float g_xh[NNODES * HD];    // projected features [N, H*D]  (51.2 MB)
__device__ __align__(16) float g_Wt[D * HD];         // W transposed [k][t]          (64 KB)
__device__ __align__(16) float g_asrc[NNODES * H];   // per-node src logits
__device__ __align__(16) float g_adst[NNODES * H];   // per-node dst logits
__device__ __align__(16) float g_w[NTOT * H];        // per-edge exp(alpha)          (13.6 MB)
__device__ __align__(16) float g_denom[NNODES * H];  // softmax denominators

// ---------------- helpers ----------------
__device__ __forceinline__ float lrelu(float a) {
    return a > 0.f ? a : 0.2f * a;
}

__device__ __forceinline__ void red_add_v4(float* ptr, float a, float b, float c, float d) {
    asm volatile(
        "{\n\t"
        ".reg .u64 p;\n\t"
        "cvta.to.global.u64 p, %0;\n\t"
        "red.global.add.v4.f32 [p], {%1, %2, %3, %4};\n\t"
        "}"
        :: "l"(ptr), "f"(a), "f"(b), "f"(c), "f"(d)
        : "memory");
}

// ---------------- K0: init out = bias, denom = 0 ----------------
__global__ void init_kernel(float* __restrict__ out, const float* __restrict__ bias) {
    int i = blockIdx.x * blockDim.x + threadIdx.x;
    if (i < NNODES * D) out[i] = bias[i & (D - 1)];
    if (i < NNODES * H) g_denom[i] = 0.f;
}

// ---------------- K1a: transpose W into g_Wt ----------------
__global__ void transpose_w_kernel(const float* __restrict__ W) {
    int i = blockIdx.x * blockDim.x + threadIdx.x;   // over HD*D = 16384
    if (i < HD * D) {
        int t = i / D;     // output column (0..255)
        int k = i % D;     // input dim (0..63)
        g_Wt[k * HD + t] = W[i];
    }
}

// ---------------- K1b: GEMM xh = x @ W.T  + per-node attention logits ----------------
#define NB 8   // nodes per block
__global__ void __launch_bounds__(256) gemm_att_kernel(
    const float* __restrict__ x,
    const float* __restrict__ att_src,
    const float* __restrict__ att_dst)
{
    __shared__ float xs[NB][D];          // 2 KB
    __shared__ float s_red[2][8][NB];    // [src/dst][warp][node]

    const int t = threadIdx.x;           // output column 0..255 (h = t/64, d = t%64)
    const int node0 = blockIdx.x * NB;

    // load NB node feature rows to shared (coalesced)
    #pragma unroll
    for (int i = t; i < NB * D; i += 256) {
        xs[i / D][i % D] = x[(node0 + i / D) * D + (i % D)];
    }
    __syncthreads();

    float acc[NB];
    #pragma unroll
    for (int i = 0; i < NB; i++) acc[i] = 0.f;

    // Wt[k][t] read is coalesced across the warp; 64 KB stays hot in L1/L2
    #pragma unroll 16
    for (int k = 0; k < D; k++) {
        const float w = g_Wt[k * HD + t];
        #pragma unroll
        for (int i = 0; i < NB; i++) acc[i] = fmaf(w, xs[i][k], acc[i]);
    }

    // store xh (coalesced)
    #pragma unroll
    for (int i = 0; i < NB; i++) g_xh[(node0 + i) * HD + t] = acc[i];

    // attention logits: a_src[n,h] = sum_d xh[n,h,d]*att_src[h,d]
    const float ast = __ldg(&att_src[t]);   // flat [H*D] indexing matches column t
    const float adt = __ldg(&att_dst[t]);

    #pragma unroll
    for (int i = 0; i < NB; i++) {
        float ps = acc[i] * ast;
        float pd = acc[i] * adt;
        #pragma unroll
        for (int o = 16; o > 0; o >>= 1) {
            ps += __shfl_down_sync(0xffffffffu, ps, o);
            pd += __shfl_down_sync(0xffffffffu, pd, o);
        }
        if ((t & 31) == 0) {
            s_red[0][t >> 5][i] = ps;
            s_red[1][t >> 5][i] = pd;
        }
    }
    __syncthreads();

    // warp w covers columns [32w, 32w+32) -> head h = w>>1 ; combine warp pairs
    if (t < 64) {
        const int which = t >> 5;          // 0 = src, 1 = dst
        const int r = t & 31;
        const int i = r >> 2;              // node 0..7
        const int h = r & 3;               // head 0..3
        const float v = s_red[which][2 * h][i] + s_red[which][2 * h + 1][i];
        float* dstp = which ? g_adst : g_asrc;
        dstp[(node0 + i) * H + h] = v;
    }
}

// ---------------- K2: per-edge exp(leaky_relu) + denominator scatter ----------------
// No max-subtraction: logits are ~N(0,sqrt(2)); max over 3.4M draws ~ 7.5 -> exp fine in fp32.
__global__ void edge_alpha_kernel(const int* __restrict__ ei) {
    const int e = blockIdx.x * blockDim.x + threadIdx.x;
    if (e >= NTOT) return;

    int src, dst;
    if (e < NEDGES) { src = ei[e]; dst = ei[NEDGES + e]; }
    else            { src = dst = e - NEDGES; }          // self-loops

    const float4 as = *(const float4*)(g_asrc + src * H);
    const float4 ad = *(const float4*)(g_adst + dst * H);

    float4 al;
    al.x = __expf(lrelu(as.x + ad.x));
    al.y = __expf(lrelu(as.y + ad.y));
    al.z = __expf(lrelu(as.z + ad.z));
    al.w = __expf(lrelu(as.w + ad.w));

    *(float4*)(g_w + e * H) = al;
    red_add_v4(g_denom + dst * H, al.x, al.y, al.z, al.w);
}

// ---------------- K3: aggregation: out[dst] += sum_h coef[h] * xh[src,h,:] ----------------
// 16 edges/block, 16 threads/edge (each handles a float4 chunk of the 64-dim output).
// Head-mean folded into coef so the scatter is only 64 floats per edge (4 vector reds).
#define EPB 16
__global__ void __launch_bounds__(256) edge_agg_kernel(
    const int* __restrict__ ei, float* __restrict__ out)
{
    __shared__ int   s_src[EPB];
    __shared__ int   s_dst[EPB];
    __shared__ __align__(16) float s_coef[EPB][H];

    const int tid = threadIdx.x;
    const int e0 = blockIdx.x * EPB;

    // phase A: load indices (16 src + 16 dst)
    if (tid < 2 * EPB) {
        const int el = tid & (EPB - 1);
        const int e = e0 + el;
        const bool is_dst = (tid >= EPB);
        int v;
        if (e < NEDGES) v = ei[e + (is_dst ? NEDGES : 0)];
        else            v = e - NEDGES;
        if (is_dst) s_dst[el] = v; else s_src[el] = v;
    }
    __syncthreads();

    // phase B: normalized coefficients (w / denom / H)
    if (tid < EPB * H) {
        const int el = tid >> 2;
        const int h = tid & 3;
        const float w = g_w[(e0 + el) * H + h];
        const float dn = g_denom[s_dst[el] * H + h];
        s_coef[el][h] = w / (dn + 1e-16f) * (1.0f / H);
    }
    __syncthreads();

    // phase C: gather + weighted sum over heads + vector reduction scatter
    const int el = tid >> 4;           // edge within block
    const int q  = tid & 15;           // float4 chunk (d = 4q..4q+3)
    const int src = s_src[el];
    const int dst = s_dst[el];

    const float c0 = s_coef[el][0];
    const float c1 = s_coef[el][1];
    const float c2 = s_coef[el][2];
    const float c3 = s_coef[el][3];

    const float4* xp = (const float4*)(g_xh + src * HD);
    const float4 v0 = xp[q];           // head 0
    const float4 v1 = xp[16 + q];      // head 1
    const float4 v2 = xp[32 + q];      // head 2
    const float4 v3 = xp[48 + q];      // head 3

    float4 m;
    m.x = c0 * v0.x + c1 * v1.x + c2 * v2.x + c3 * v3.x;
    m.y = c0 * v0.y + c1 * v1.y + c2 * v2.y + c3 * v3.y;
    m.z = c0 * v0.z + c1 * v1.z + c2 * v2.z + c3 * v3.z;
    m.w = c0 * v0.w + c1 * v1.w + c2 * v2.w + c3 * v3.w;

    red_add_v4(out + dst * D + q * 4, m.x, m.y, m.z, m.w);
}

// ---------------- launch ----------------
extern "C" void kernel_launch(void* const* d_in, const int* in_sizes, int n_in,
                              void* d_out, int out_size) {
    const float* x       = (const float*)d_in[0];
    const int*   ei      = (const int*)  d_in[1];
    const float* W       = (const float*)d_in[2];
    const float* att_src = (const float*)d_in[3];
    const float* att_dst = (const float*)d_in[4];
    const float* bias    = (const float*)d_in[5];
    float* out = (float*)d_out;

    // K0: init output to bias, zero denominators
    init_kernel<<<(NNODES * D + 255) / 256, 256>>>(out, bias);

    // K1a: transpose W
    transpose_w_kernel<<<(HD * D + 255) / 256, 256>>>(W);

    // K1b: projection GEMM + attention logits
    gemm_att_kernel<<<NNODES / NB, 256>>>(x, att_src, att_dst);

    // K2: per-edge exp(leaky_relu) + denominator accumulation
    edge_alpha_kernel<<<(NTOT + 255) / 256, 256>>>(ei);

    // K3: weighted aggregation
    edge_agg_kernel<<<NTOT / EPB, 256>>>(ei, out);
}

// round 2
// speedup vs baseline: 1.0788x; 1.0788x over previous
#include <cuda_runtime.h>
#include <cuda_fp16.h>

// Problem constants (fixed by the dataset)
#define NNODES 50000
#define NEDGES 800000
#define NTOT   (NEDGES + NNODES)   // edges + self loops = 850000
#define D      64
#define H      4
#define HD     256                 // H*D

// -------- scratch (static device globals; no allocation allowed) --------
__device__ __align__(16) __half g_xh[NNODES * HD];   // projected features fp16 [N, H*D] (25.6 MB)
__device__ __align__(16) float g_Wt[D * HD];         // W transposed [k][t]              (64 KB)
__device__ __align__(16) float g_asrc[NNODES * H];   // per-node src logits
__device__ __align__(16) float g_adst[NNODES * H];   // per-node dst logits
__device__ __align__(16) float g_w[NTOT * H];        // per-edge exp(alpha)              (13.6 MB)
__device__ __align__(16) float g_denom[NNODES * H];  // softmax denominators

// ---------------- helpers ----------------
__device__ __forceinline__ float lrelu(float a) {
    return a > 0.f ? a : 0.2f * a;
}

__device__ __forceinline__ void red_add_v4(float* ptr, float a, float b, float c, float d) {
    asm volatile(
        "{\n\t"
        ".reg .u64 p;\n\t"
        "cvta.to.global.u64 p, %0;\n\t"
        "red.global.add.v4.f32 [p], {%1, %2, %3, %4};\n\t"
        "}"
        :: "l"(ptr), "f"(a), "f"(b), "f"(c), "f"(d)
        : "memory");
}

// ---------------- K0: init out = bias, denom = 0 ----------------
__global__ void init_kernel(float* __restrict__ out, const float* __restrict__ bias) {
    int i = blockIdx.x * blockDim.x + threadIdx.x;
    if (i < NNODES * D) out[i] = bias[i & (D - 1)];
    if (i < NNODES * H) g_denom[i] = 0.f;
}

// ---------------- K1a: transpose W into g_Wt ----------------
__global__ void transpose_w_kernel(const float* __restrict__ W) {
    int i = blockIdx.x * blockDim.x + threadIdx.x;   // over HD*D = 16384
    if (i < HD * D) {
        int t = i / D;     // output column (0..255)
        int k = i % D;     // input dim (0..63)
        g_Wt[k * HD + t] = W[i];
    }
}

// ---------------- K1b: GEMM xh = x @ W.T (fp16 store) + per-node attention logits ----------------
#define NB 8   // nodes per block
__global__ void __launch_bounds__(256) gemm_att_kernel(
    const float* __restrict__ x,
    const float* __restrict__ att_src,
    const float* __restrict__ att_dst)
{
    __shared__ float xs[NB][D];          // 2 KB
    __shared__ float s_red[2][8][NB];    // [src/dst][warp][node]

    const int t = threadIdx.x;           // output column 0..255 (h = t/64, d = t%64)
    const int node0 = blockIdx.x * NB;

    // load NB node feature rows to shared (coalesced)
    #pragma unroll
    for (int i = t; i < NB * D; i += 256) {
        xs[i / D][i % D] = x[(node0 + i / D) * D + (i % D)];
    }
    __syncthreads();

    float acc[NB];
    #pragma unroll
    for (int i = 0; i < NB; i++) acc[i] = 0.f;

    // Wt[k][t] read is coalesced across the warp; 64 KB stays hot in L1/L2
    #pragma unroll 16
    for (int k = 0; k < D; k++) {
        const float w = g_Wt[k * HD + t];
        #pragma unroll
        for (int i = 0; i < NB; i++) acc[i] = fmaf(w, xs[i][k], acc[i]);
    }

    // store xh as fp16 (coalesced 2B/thread, 512B per warp store)
    #pragma unroll
    for (int i = 0; i < NB; i++) g_xh[(node0 + i) * HD + t] = __float2half_rn(acc[i]);

    // attention logits (fp32): a_src[n,h] = sum_d xh[n,h,d]*att_src[h,d]
    const float ast = __ldg(&att_src[t]);   // flat [H*D] indexing matches column t
    const float adt = __ldg(&att_dst[t]);

    #pragma unroll
    for (int i = 0; i < NB; i++) {
        float ps = acc[i] * ast;
        float pd = acc[i] * adt;
        #pragma unroll
        for (int o = 16; o > 0; o >>= 1) {
            ps += __shfl_down_sync(0xffffffffu, ps, o);
            pd += __shfl_down_sync(0xffffffffu, pd, o);
        }
        if ((t & 31) == 0) {
            s_red[0][t >> 5][i] = ps;
            s_red[1][t >> 5][i] = pd;
        }
    }
    __syncthreads();

    // warp w covers columns [32w, 32w+32) -> head h = w>>1 ; combine warp pairs
    if (t < 64) {
        const int which = t >> 5;          // 0 = src, 1 = dst
        const int r = t & 31;
        const int i = r >> 2;              // node 0..7
        const int h = r & 3;               // head 0..3
        const float v = s_red[which][2 * h][i] + s_red[which][2 * h + 1][i];
        float* dstp = which ? g_adst : g_asrc;
        dstp[(node0 + i) * H + h] = v;
    }
}

// ---------------- K2: per-edge exp(leaky_relu) + denominator scatter (2 edges/thread) ----------------
// No max-subtraction: logits ~N(0,sqrt(2)); max over 3.4M draws ~7.5 -> exp fine in fp32.
__global__ void edge_alpha_kernel(const int* __restrict__ ei) {
    const int e = 2 * (blockIdx.x * blockDim.x + threadIdx.x);
    if (e >= NTOT) return;

    int s0, d0, s1, d1;
    if (e + 1 < NEDGES) {
        const int2 sp = *(const int2*)(ei + e);
        const int2 dp = *(const int2*)(ei + NEDGES + e);
        s0 = sp.x; s1 = sp.y; d0 = dp.x; d1 = dp.y;
    } else {
        s0 = d0 = e - NEDGES;
        s1 = d1 = e + 1 - NEDGES;
    }

    // issue all four 16B logit loads before any compute (MLP=4)
    const float4 as0 = *(const float4*)(g_asrc + s0 * H);
    const float4 ad0 = *(const float4*)(g_adst + d0 * H);
    const float4 as1 = *(const float4*)(g_asrc + s1 * H);
    const float4 ad1 = *(const float4*)(g_adst + d1 * H);

    float4 a0, a1;
    a0.x = __expf(lrelu(as0.x + ad0.x));
    a0.y = __expf(lrelu(as0.y + ad0.y));
    a0.z = __expf(lrelu(as0.z + ad0.z));
    a0.w = __expf(lrelu(as0.w + ad0.w));
    a1.x = __expf(lrelu(as1.x + ad1.x));
    a1.y = __expf(lrelu(as1.y + ad1.y));
    a1.z = __expf(lrelu(as1.z + ad1.z));
    a1.w = __expf(lrelu(as1.w + ad1.w));

    *(float4*)(g_w + e * H) = a0;
    *(float4*)(g_w + (e + 1) * H) = a1;
    red_add_v4(g_denom + d0 * H, a0.x, a0.y, a0.z, a0.w);
    red_add_v4(g_denom + d1 * H, a1.x, a1.y, a1.z, a1.w);
}

// ---------------- K3: aggregation: out[dst] += (1/H) sum_h coef[h] * xh[src,h,:] ----------------
// 32 edges/block, 8 threads/edge; each thread handles 8 output dims.
// Gathers are LDG.128 of half2x4 (16B per head, coalesced across the edge's 8 threads).
#define EPB 32
__global__ void __launch_bounds__(256) edge_agg_kernel(
    const int* __restrict__ ei, float* __restrict__ out)
{
    __shared__ int   s_src[EPB];
    __shared__ int   s_dst[EPB];
    __shared__ __align__(16) float s_coef[EPB][H];

    const int tid = threadIdx.x;
    const int e0 = blockIdx.x * EPB;

    // phase A: load indices (32 src + 32 dst)
    if (tid < 2 * EPB) {
        const int el = tid & (EPB - 1);
        const int e = e0 + el;
        const bool is_dst = (tid >= EPB);
        int v = 0;
        if (e < NTOT) v = (e < NEDGES) ? ei[e + (is_dst ? NEDGES : 0)] : (e - NEDGES);
        if (is_dst) s_dst[el] = v; else s_src[el] = v;
    }
    __syncthreads();

    // phase B: normalized coefficients (w / denom / H)
    if (tid < EPB * H) {
        const int el = tid >> 2;
        const int h = tid & 3;
        const int e = e0 + el;
        float c = 0.f;
        if (e < NTOT) {
            const float w = g_w[e * H + h];
            const float dn = g_denom[s_dst[el] * H + h];
            c = w / (dn + 1e-16f) * (1.0f / H);
        }
        s_coef[el][h] = c;
    }
    __syncthreads();

    // phase C: fp16 gather + weighted head-sum + vector reduction scatter
    const int el = tid >> 3;           // edge within block (0..31)
    const int q  = tid & 7;            // chunk: output dims d = 8q..8q+7
    if (e0 + el >= NTOT) return;

    const int src = s_src[el];
    const int dst = s_dst[el];

    float m[8];
    #pragma unroll
    for (int j = 0; j < 8; j++) m[j] = 0.f;

    const uint4* xp = (const uint4*)(g_xh + src * HD);   // 16 halves per uint4... (8 halves = 16B)
    #pragma unroll
    for (int h = 0; h < H; h++) {
        const float c = s_coef[el][h];
        // half index base: h*64 + 8q ; 8 halves = one 16B load
        const uint4 v = xp[h * 8 + q];
        const float2 f0 = __half22float2(*(const __half2*)&v.x);
        const float2 f1 = __half22float2(*(const __half2*)&v.y);
        const float2 f2 = __half22float2(*(const __half2*)&v.z);
        const float2 f3 = __half22float2(*(const __half2*)&v.w);
        m[0] = fmaf(c, f0.x, m[0]);
        m[1] = fmaf(c, f0.y, m[1]);
        m[2] = fmaf(c, f1.x, m[2]);
        m[3] = fmaf(c, f1.y, m[3]);
        m[4] = fmaf(c, f2.x, m[4]);
        m[5] = fmaf(c, f2.y, m[5]);
        m[6] = fmaf(c, f3.x, m[6]);
        m[7] = fmaf(c, f3.y, m[7]);
    }

    float* op = out + dst * D + q * 8;
    red_add_v4(op,     m[0], m[1], m[2], m[3]);
    red_add_v4(op + 4, m[4], m[5], m[6], m[7]);
}

// ---------------- launch ----------------
extern "C" void kernel_launch(void* const* d_in, const int* in_sizes, int n_in,
                              void* d_out, int out_size) {
    const float* x       = (const float*)d_in[0];
    const int*   ei      = (const int*)  d_in[1];
    const float* W       = (const float*)d_in[2];
    const float* att_src = (const float*)d_in[3];
    const float* att_dst = (const float*)d_in[4];
    const float* bias    = (const float*)d_in[5];
    float* out = (float*)d_out;

    // K0: init output to bias, zero denominators
    init_kernel<<<(NNODES * D + 255) / 256, 256>>>(out, bias);

    // K1a: transpose W
    transpose_w_kernel<<<(HD * D + 255) / 256, 256>>>(W);

    // K1b: projection GEMM + attention logits
    gemm_att_kernel<<<NNODES / NB, 256>>>(x, att_src, att_dst);

    // K2: per-edge exp(leaky_relu) + denominator accumulation (2 edges/thread)
    edge_alpha_kernel<<<(NTOT / 2 + 255) / 256, 256>>>(ei);

    // K3: weighted aggregation
    edge_agg_kernel<<<(NTOT + EPB - 1) / EPB, 256>>>(ei, out);
}

// round 4
// speedup vs baseline: 1.3915x; 1.2899x over previous
#include <cuda_runtime.h>
#include <cuda_fp16.h>
#include <cstdint>

// Problem constants (fixed by the dataset)
#define NNODES 50000
#define NEDGES 800000
#define NTOT   (NEDGES + NNODES)   // edges + self loops = 850000
#define D      64
#define H      4
#define HD     256                 // H*D

// -------- scratch (static device globals; no allocation allowed) --------
__device__ __align__(16) __half g_xh[NNODES * HD];   // projected features fp16 [N, H*D] (25.6 MB)
__device__ __align__(16) __half g_Wh[HD * D];        // W in fp16, original [t][k] layout (32 KB)
__device__ __align__(16) float g_asrc[NNODES * H];   // per-node src logits
__device__ __align__(16) float g_adst[NNODES * H];   // per-node dst logits
__device__ __align__(16) float g_w[NTOT * H];        // per-edge exp(alpha)              (13.6 MB)
__device__ __align__(16) float g_denom[NNODES * H];  // softmax denominators

// ---------------- helpers ----------------
__device__ __forceinline__ float lrelu(float a) {
    return a > 0.f ? a : 0.2f * a;
}

__device__ __forceinline__ void red_add_v4(float* ptr, float a, float b, float c, float d) {
    asm volatile(
        "{\n\t"
        ".reg .u64 p;\n\t"
        "cvta.to.global.u64 p, %0;\n\t"
        "red.global.add.v4.f32 [p], {%1, %2, %3, %4};\n\t"
        "}"
        :: "l"(ptr), "f"(a), "f"(b), "f"(c), "f"(d)
        : "memory");
}

__device__ __forceinline__ unsigned f2_to_h2(float2 f) {
    __half2 h = __floats2half2_rn(f.x, f.y);
    return *(unsigned*)&h;
}

// ---------------- K0: init out = bias, denom = 0 ----------------
__global__ void init_kernel(float* __restrict__ out, const float* __restrict__ bias) {
    int i = blockIdx.x * blockDim.x + threadIdx.x;
    if (i < NNODES * D) out[i] = bias[i & (D - 1)];
    if (i < NNODES * H) g_denom[i] = 0.f;
}

// ---------------- K1a: convert W to fp16 (keeps [t][k] layout == col-major B) ----------------
__global__ void prep_w_kernel(const float* __restrict__ W) {
    int i = blockIdx.x * blockDim.x + threadIdx.x;   // over HD*D = 16384
    if (i < HD * D) g_Wh[i] = __float2half_rn(W[i]);
}

// ---------------- K1b: tensor-core GEMM xh = x @ W.T + per-node attention logits ----------------
// mma.sync.m16n8k16.row.col.f32.f16.f16.f32
// Block: 256 threads = 8 warps; warpM = wid>>2 (2 M-tiles of 16 nodes), head = wid&3 (64 cols each).
// A fragments loaded directly from global fp32 x (read once), B fragments from g_Wh (L1-resident).
__global__ void __launch_bounds__(256) gemm_att_kernel(
    const float* __restrict__ x,
    const float* __restrict__ att_src,
    const float* __restrict__ att_dst)
{
    const int lane  = threadIdx.x & 31;
    const int wid   = threadIdx.x >> 5;
    const int warpM = wid >> 2;          // 0..1
    const int head  = wid & 3;           // warp's head == its 64-col slab
    const int g     = lane >> 2;         // group id 0..7
    const int tg    = lane & 3;          // thread-in-group 0..3

    const int r0 = blockIdx.x * 32 + warpM * 16 + g;   // node row (top half)
    const int r1 = r0 + 8;                              // node row (bottom half)
    const int colbase = head * 64;

    // acc[nt][0..3]: D[g][tg*2], D[g][tg*2+1], D[g+8][tg*2], D[g+8][tg*2+1]
    // for output cols colbase + nt*8 + tg*2 (+1)
    float acc[8][4];
    #pragma unroll
    for (int nt = 0; nt < 8; nt++)
        #pragma unroll
        for (int j = 0; j < 4; j++) acc[nt][j] = 0.f;

    const bool v0 = (r0 < NNODES);
    const bool v1 = (r1 < NNODES);
    const float2 fz = make_float2(0.f, 0.f);

    #pragma unroll
    for (int ks = 0; ks < 4; ks++) {
        const int k = ks * 16;
        // A fragment (16x16 row-major): 4 regs
        const float2 fa0 = v0 ? *(const float2*)(x + r0 * D + k + tg * 2)     : fz;
        const float2 fa1 = v1 ? *(const float2*)(x + r1 * D + k + tg * 2)     : fz;
        const float2 fa2 = v0 ? *(const float2*)(x + r0 * D + k + 8 + tg * 2) : fz;
        const float2 fa3 = v1 ? *(const float2*)(x + r1 * D + k + 8 + tg * 2) : fz;
        const unsigned a0 = f2_to_h2(fa0);
        const unsigned a1 = f2_to_h2(fa1);
        const unsigned a2 = f2_to_h2(fa2);
        const unsigned a3 = f2_to_h2(fa3);

        #pragma unroll
        for (int nt = 0; nt < 8; nt++) {
            const int n = colbase + nt * 8 + g;   // output column for B fragment
            // B col-major (16x8): b0 = {B[tg*2][n], B[tg*2+1][n]} = Wh[n][k+tg*2 .. +1]
            const unsigned b0 = *(const unsigned*)(g_Wh + n * D + k + tg * 2);
            const unsigned b1 = *(const unsigned*)(g_Wh + n * D + k + 8 + tg * 2);
            asm volatile(
                "mma.sync.aligned.m16n8k16.row.col.f32.f16.f16.f32 "
                "{%0,%1,%2,%3}, {%4,%5,%6,%7}, {%8,%9}, {%0,%1,%2,%3};"
                : "+f"(acc[nt][0]), "+f"(acc[nt][1]), "+f"(acc[nt][2]), "+f"(acc[nt][3])
                : "r"(a0), "r"(a1), "r"(a2), "r"(a3), "r"(b0), "r"(b1));
        }
    }

    // store xh as fp16 (half2 stores; 4 tg-lanes form 16B contiguous runs)
    #pragma unroll
    for (int nt = 0; nt < 8; nt++) {
        const int c = colbase + nt * 8 + tg * 2;
        if (v0) *(__half2*)(g_xh + r0 * HD + c) = __floats2half2_rn(acc[nt][0], acc[nt][1]);
        if (v1) *(__half2*)(g_xh + r1 * HD + c) = __floats2half2_rn(acc[nt][2], acc[nt][3]);
    }

    // attention logits (fp32 accumulators, per-head dot with att vectors)
    float ps0 = 0.f, ps1 = 0.f, pd0 = 0.f, pd1 = 0.f;
    #pragma unroll
    for (int nt = 0; nt < 8; nt++) {
        const int c = colbase + nt * 8 + tg * 2;
        const float2 as = *(const float2*)(att_src + c);
        const float2 ad = *(const float2*)(att_dst + c);
        ps0 += acc[nt][0] * as.x + acc[nt][1] * as.y;
        ps1 += acc[nt][2] * as.x + acc[nt][3] * as.y;
        pd0 += acc[nt][0] * ad.x + acc[nt][1] * ad.y;
        pd1 += acc[nt][2] * ad.x + acc[nt][3] * ad.y;
    }
    // reduce across the 4 tg-lanes of each group
    ps0 += __shfl_down_sync(0xffffffffu, ps0, 2); ps0 += __shfl_down_sync(0xffffffffu, ps0, 1);
    ps1 += __shfl_down_sync(0xffffffffu, ps1, 2); ps1 += __shfl_down_sync(0xffffffffu, ps1, 1);
    pd0 += __shfl_down_sync(0xffffffffu, pd0, 2); pd0 += __shfl_down_sync(0xffffffffu, pd0, 1);
    pd1 += __shfl_down_sync(0xffffffffu, pd1, 2); pd1 += __shfl_down_sync(0xffffffffu, pd1, 1);

    if (tg == 0) {
        if (v0) { g_asrc[r0 * H + head] = ps0; g_adst[r0 * H + head] = pd0; }
        if (v1) { g_asrc[r1 * H + head] = ps1; g_adst[r1 * H + head] = pd1; }
    }
}

// ---------------- K2: per-edge exp(leaky_relu) + denominator scatter ----------------
// (R1 form: 1 edge/thread measured faster than 2 edges/thread.)
// No max-subtraction: logits ~N(0,sqrt(2)); max over 3.4M draws ~7.5 -> exp fine in fp32.
__global__ void edge_alpha_kernel(const int* __restrict__ ei) {
    const int e = blockIdx.x * blockDim.x + threadIdx.x;
    if (e >= NTOT) return;

    int src, dst;
    if (e < NEDGES) { src = ei[e]; dst = ei[NEDGES + e]; }
    else            { src = dst = e - NEDGES; }          // self-loops

    const float4 as = *(const float4*)(g_asrc + src * H);
    const float4 ad = *(const float4*)(g_adst + dst * H);

    float4 al;
    al.x = __expf(lrelu(as.x + ad.x));
    al.y = __expf(lrelu(as.y + ad.y));
    al.z = __expf(lrelu(as.z + ad.z));
    al.w = __expf(lrelu(as.w + ad.w));

    *(float4*)(g_w + e * H) = al;
    red_add_v4(g_denom + dst * H, al.x, al.y, al.z, al.w);
}

// ---------------- K3: aggregation: out[dst] += (1/H) sum_h coef[h] * xh[src,h,:] ----------------
// 32 edges/block, 8 threads/edge; each thread handles 8 output dims.
#define EPB 32
__global__ void __launch_bounds__(256) edge_agg_kernel(
    const int* __restrict__ ei, float* __restrict__ out)
{
    __shared__ int   s_src[EPB];
    __shared__ int   s_dst[EPB];
    __shared__ __align__(16) float s_coef[EPB][H];

    const int tid = threadIdx.x;
    const int e0 = blockIdx.x * EPB;

    // phase A: load indices (32 src + 32 dst)
    if (tid < 2 * EPB) {
        const int el = tid & (EPB - 1);
        const int e = e0 + el;
        const bool is_dst = (tid >= EPB);
        int v = 0;
        if (e < NTOT) v = (e < NEDGES) ? ei[e + (is_dst ? NEDGES : 0)] : (e - NEDGES);
        if (is_dst) s_dst[el] = v; else s_src[el] = v;
    }
    __syncthreads();

    // phase B: normalized coefficients (w / denom / H)
    if (tid < EPB * H) {
        const int el = tid >> 2;
        const int h = tid & 3;
        const int e = e0 + el;
        float c = 0.f;
        if (e < NTOT) {
            const float w = g_w[e * H + h];
            const float dn = g_denom[s_dst[el] * H + h];
            c = w / (dn + 1e-16f) * (1.0f / H);
        }
        s_coef[el][h] = c;
    }
    __syncthreads();

    // phase C: fp16 gather + weighted head-sum + vector reduction scatter
    const int el = tid >> 3;           // edge within block (0..31)
    const int q  = tid & 7;            // chunk: output dims d = 8q..8q+7
    if (e0 + el >= NTOT) return;

    const int src = s_src[el];
    const int dst = s_dst[el];

    float m[8];
    #pragma unroll
    for (int j = 0; j < 8; j++) m[j] = 0.f;

    const uint4* xp = (const uint4*)(g_xh + src * HD);
    #pragma unroll
    for (int h = 0; h < H; h++) {
        const float c = s_coef[el][h];
        const uint4 v = xp[h * 8 + q];   // 8 halves = 16B per head
        const float2 f0 = __half22float2(*(const __half2*)&v.x);
        const float2 f1 = __half22float2(*(const __half2*)&v.y);
        const float2 f2 = __half22float2(*(const __half2*)&v.z);
        const float2 f3 = __half22float2(*(const __half2*)&v.w);
        m[0] = fmaf(c, f0.x, m[0]);
        m[1] = fmaf(c, f0.y, m[1]);
        m[2] = fmaf(c, f1.x, m[2]);
        m[3] = fmaf(c, f1.y, m[3]);
        m[4] = fmaf(c, f2.x, m[4]);
        m[5] = fmaf(c, f2.y, m[5]);
        m[6] = fmaf(c, f3.x, m[6]);
        m[7] = fmaf(c, f3.y, m[7]);
    }

    float* op = out + dst * D + q * 8;
    red_add_v4(op,     m[0], m[1], m[2], m[3]);
    red_add_v4(op + 4, m[4], m[5], m[6], m[7]);
}

// ---------------- launch ----------------
extern "C" void kernel_launch(void* const* d_in, const int* in_sizes, int n_in,
                              void* d_out, int out_size) {
    const float* x       = (const float*)d_in[0];
    const int*   ei      = (const int*)  d_in[1];
    const float* W       = (const float*)d_in[2];
    const float* att_src = (const float*)d_in[3];
    const float* att_dst = (const float*)d_in[4];
    const float* bias    = (const float*)d_in[5];
    float* out = (float*)d_out;

    // K0: init output to bias, zero denominators
    init_kernel<<<(NNODES * D + 255) / 256, 256>>>(out, bias);

    // K1a: W -> fp16
    prep_w_kernel<<<(HD * D + 255) / 256, 256>>>(W);

    // K1b: tensor-core projection GEMM + attention logits (32 nodes/block)
    gemm_att_kernel<<<(NNODES + 31) / 32, 256>>>(x, att_src, att_dst);

    // K2: per-edge exp(leaky_relu) + denominator accumulation
    edge_alpha_kernel<<<(NTOT + 255) / 256, 256>>>(ei);

    // K3: weighted aggregation
    edge_agg_kernel<<<(NTOT + EPB - 1) / EPB, 256>>>(ei, out);
}